// round 1
// baseline (speedup 1.0000x reference)
#include <cuda_runtime.h>
#include <cuda_bf16.h>

// Problem constants
#define BB 4
#define CC 64
#define HH 96
#define WW 96
#define TT 18     // offset channels
#define KK 9      // taps
#define OO 64
#define NPIX (BB*HH*WW)   // 36864

// -------- scratch (device globals; no allocation allowed) --------
__device__ float g_xn[NPIX * CC];              // NHWC x          9.4 MB
__device__ float g_offs[NPIX * TT];            // [pix][18]       2.65 MB
__device__ float g_woff[KK * 16 * TT * 4];     // [tap][c4][t][cc] 41 KB
__device__ float g_wdc[KK * CC * OO];          // [k][c][o]       147 KB

// ---------------- NCHW -> NHWC transpose ----------------
__global__ void k_transpose(const float* __restrict__ x) {
    __shared__ float tile[64][97];
    int bh = blockIdx.x;                 // b*96 + h
    int b = bh / HH, h = bh % HH;
    const float* src = x + ((size_t)b * CC) * (HH * WW) + (size_t)h * WW;
    for (int i = threadIdx.x; i < CC * WW; i += blockDim.x) {
        int c = i / WW, w = i % WW;
        tile[c][w] = src[(size_t)c * (HH * WW) + w];
    }
    __syncthreads();
    float* dst = g_xn + (size_t)bh * WW * CC;
    for (int i = threadIdx.x; i < WW * CC; i += blockDim.x) {
        int w = i / CC, c = i % CC;
        dst[i] = tile[c][w];
    }
}

// ---------------- weight repack ----------------
__global__ void k_repack(const float* __restrict__ w_off, const float* __restrict__ w_dc) {
    int i = blockIdx.x * blockDim.x + threadIdx.x;
    if (i < TT * CC * KK) {
        // w_off flat [t][c][ky][kx] -> g_woff[tap][c>>2][t][c&3]
        int t = i / (CC * KK);
        int r = i % (CC * KK);
        int c = r / KK;
        int tap = r % KK;
        g_woff[((tap * 16 + (c >> 2)) * TT + t) * 4 + (c & 3)] = w_off[i];
    }
    if (i < OO * CC * KK) {
        // w_dc flat [o][c][ky][kx] -> g_wdc[k][c][o]
        int o = i / (CC * KK);
        int r = i % (CC * KK);
        int c = r / KK;
        int k = r % KK;
        g_wdc[(k * CC + c) * OO + o] = w_dc[i];
    }
}

// ---------------- offset conv: offs[pix][18] ----------------
__global__ void k_offconv(const float* __restrict__ b_off) {
    __shared__ float sw[KK * 16 * TT * 4];   // 41.5 KB
    for (int i = threadIdx.x; i < KK * 16 * TT * 4; i += blockDim.x)
        sw[i] = g_woff[i];
    __syncthreads();

    int pix = blockIdx.x * blockDim.x + threadIdx.x;
    if (pix >= NPIX) return;
    int w = pix % WW;
    int h = (pix / WW) % HH;
    int b = pix / (HH * WW);

    float acc[TT];
#pragma unroll
    for (int t = 0; t < TT; t++) acc[t] = b_off[t];

    for (int tap = 0; tap < KK; tap++) {
        int y = h + tap / 3 - 1;
        int x = w + tap % 3 - 1;
        if ((unsigned)y >= (unsigned)HH || (unsigned)x >= (unsigned)WW) continue;
        const float4* row = (const float4*)(g_xn + ((size_t)((b * HH + y) * WW + x)) * CC);
        const float4* wrow = (const float4*)(sw + tap * 16 * TT * 4);
#pragma unroll 2
        for (int c4 = 0; c4 < 16; c4++) {
            float4 xv = row[c4];
#pragma unroll
            for (int t = 0; t < TT; t++) {
                float4 wv = wrow[c4 * TT + t];
                acc[t] += xv.x * wv.x + xv.y * wv.y + xv.z * wv.z + xv.w * wv.w;
            }
        }
    }
    float* op = g_offs + (size_t)pix * TT;
#pragma unroll
    for (int t = 0; t < TT; t++) op[t] = acc[t];
}

// ---------------- main fused gather + GEMM ----------------
// Tile: 32 pixels (same row) x 64 outputs. 256 threads: thread = (p = tid>>3, og = (tid&7)*8)
#define TP 32
#define SA_STRIDE 68   // pad: stride*4 = 272 B, 16B-aligned, bank shift of 4 per row

__global__ void k_main(const float* __restrict__ b_dc, float* __restrict__ out) {
    __shared__ float sA[TP][SA_STRIDE];   // samp[p][c]   8.7 KB
    __shared__ float sW[CC * OO];         // wk[c][o]     16 KB (reused as out tile)
    __shared__ float sOff[TP][TT];        // 2.3 KB

    int tile = blockIdx.x;                // 1152 tiles, 3 per row
    int pix0 = tile * TP;
    int b = pix0 / (HH * WW);
    int rem = pix0 % (HH * WW);
    int h = rem / WW;
    int w0 = rem % WW;

    int tid = threadIdx.x;
    int p = tid >> 3;                 // pixel within tile
    int og = (tid & 7) * 8;           // output base

    for (int i = tid; i < TP * TT; i += 256)
        sOff[i / TT][i % TT] = g_offs[(size_t)pix0 * TT + i];

    float acc[8];
#pragma unroll
    for (int j = 0; j < 8; j++) acc[j] = b_dc[og + j];

    const float* xb = g_xn + (size_t)b * (HH * WW) * CC;
    int pw = w0 + p;

    for (int k = 0; k < KK; k++) {
        __syncthreads();   // protect sA/sW reuse (also covers sOff on k==0)

        // stage w_dc[k][c][o] into smem
        const float* wk = g_wdc + k * CC * OO;
        for (int i = tid; i < CC * OO; i += 256) sW[i] = wk[i];

        // gather: 8 threads per pixel, each covers 8 channels (2 float4)
        {
            float dy = sOff[p][2 * k];
            float dx = sOff[p][2 * k + 1];
            float py = (float)h + (float)(k / 3 - 1) + dy;
            float px = (float)pw + (float)(k % 3 - 1) + dx;
            float y0f = floorf(py), x0f = floorf(px);
            float ly = py - y0f, lx = px - x0f;
            int y0 = (int)y0f, x0 = (int)x0f;
            int y1 = y0 + 1, x1 = x0 + 1;
            float w00 = (1.f - ly) * (1.f - lx);
            float w01 = (1.f - ly) * lx;
            float w10 = ly * (1.f - lx);
            float w11 = ly * lx;
            bool vy0 = (unsigned)y0 < (unsigned)HH, vy1 = (unsigned)y1 < (unsigned)HH;
            bool vx0 = (unsigned)x0 < (unsigned)WW, vx1 = (unsigned)x1 < (unsigned)WW;
            w00 *= (float)(vy0 && vx0);
            w01 *= (float)(vy0 && vx1);
            w10 *= (float)(vy1 && vx0);
            w11 *= (float)(vy1 && vx1);
            int yc0 = min(max(y0, 0), HH - 1), yc1 = min(max(y1, 0), HH - 1);
            int xc0 = min(max(x0, 0), WW - 1), xc1 = min(max(x1, 0), WW - 1);
            const float4* r00 = (const float4*)(xb + (size_t)(yc0 * WW + xc0) * CC);
            const float4* r01 = (const float4*)(xb + (size_t)(yc0 * WW + xc1) * CC);
            const float4* r10 = (const float4*)(xb + (size_t)(yc1 * WW + xc0) * CC);
            const float4* r11 = (const float4*)(xb + (size_t)(yc1 * WW + xc1) * CC);
            int cq = (tid & 7) * 2;
#pragma unroll
            for (int q = 0; q < 2; q++) {
                float4 a = r00[cq + q], bb2 = r01[cq + q];
                float4 c2 = r10[cq + q], d2 = r11[cq + q];
                float4 s;
                s.x = w00 * a.x + w01 * bb2.x + w10 * c2.x + w11 * d2.x;
                s.y = w00 * a.y + w01 * bb2.y + w10 * c2.y + w11 * d2.y;
                s.z = w00 * a.z + w01 * bb2.z + w10 * c2.z + w11 * d2.z;
                s.w = w00 * a.w + w01 * bb2.w + w10 * c2.w + w11 * d2.w;
                *(float4*)&sA[p][(cq + q) * 4] = s;
            }
        }
        __syncthreads();

        // GEMM accumulation for this k: acc[o] += samp[p][c] * w[c][o]
#pragma unroll 4
        for (int c = 0; c < CC; c += 4) {
            float4 v = *(const float4*)&sA[p][c];
#pragma unroll
            for (int j = 0; j < 4; j++) {
                float vv = (j == 0) ? v.x : (j == 1) ? v.y : (j == 2) ? v.z : v.w;
                float4 wv0 = *(const float4*)&sW[(c + j) * OO + og];
                float4 wv1 = *(const float4*)&sW[(c + j) * OO + og + 4];
                acc[0] += vv * wv0.x; acc[1] += vv * wv0.y;
                acc[2] += vv * wv0.z; acc[3] += vv * wv0.w;
                acc[4] += vv * wv1.x; acc[5] += vv * wv1.y;
                acc[6] += vv * wv1.z; acc[7] += vv * wv1.w;
            }
        }
    }

    // stage output through smem for coalesced NCHW writes
    __syncthreads();
    float (*oT)[33] = (float(*)[33])sW;    // 64 x 33 floats = 8.4 KB (fits in sW)
#pragma unroll
    for (int j = 0; j < 8; j++) oT[og + j][p] = acc[j];
    __syncthreads();
    for (int i = tid; i < TP * OO; i += 256) {
        int o = i >> 5;          // /32
        int p2 = i & 31;
        out[(((size_t)b * OO + o) * HH + h) * WW + w0 + p2] = oT[o][p2];
    }
}

// ---------------- launch ----------------
extern "C" void kernel_launch(void* const* d_in, const int* in_sizes, int n_in,
                              void* d_out, int out_size) {
    const float* x     = (const float*)d_in[0];
    const float* w_off = (const float*)d_in[1];
    const float* b_off = (const float*)d_in[2];
    const float* w_dc  = (const float*)d_in[3];
    const float* b_dc  = (const float*)d_in[4];
    float* out = (float*)d_out;

    k_transpose<<<BB * HH, 256>>>(x);
    k_repack<<<(OO * CC * KK + 255) / 256, 256>>>(w_off, w_dc);
    k_offconv<<<NPIX / 128, 128>>>(b_off);
    k_main<<<NPIX / TP, 256>>>(b_dc, out);
}

// round 2
// speedup vs baseline: 2.8512x; 2.8512x over previous
#include <cuda_runtime.h>

#define BB 4
#define CC 64
#define HH 96
#define WW 96
#define TT 18
#define KK 9
#define OO 64
#define HWIMG (HH*WW)          // 9216
#define NPIX (BB*HWIMG)        // 36864
#define TPX 256                // pixels per tile
#define NTILE (NPIX/TPX)       // 144
#define SAS 260                // sA row stride in floats (16B-aligned, conflict-friendly)

// -------- scratch (device globals; no allocation allowed) --------
__device__ float g_xn[NPIX * CC];              // NHWC x
__device__ float g_offs[NPIX * TT];            // [pix][18]
__device__ float g_woff[KK * 16 * TT * 4];     // [tap][c4][t][4]
__device__ float g_wdc[KK * CC * OO];          // [k][c][o]

// ---------------- NCHW -> NHWC transpose ----------------
__global__ void k_transpose(const float* __restrict__ x) {
    __shared__ float tile[64][97];
    int bh = blockIdx.x;                 // b*96 + h
    int b = bh / HH;
    const float* src = x + ((size_t)b * CC) * HWIMG + (size_t)(bh % HH) * WW;
    for (int i = threadIdx.x; i < CC * WW; i += blockDim.x) {
        int c = i / WW, w = i % WW;
        tile[c][w] = src[(size_t)c * HWIMG + w];
    }
    __syncthreads();
    float* dst = g_xn + (size_t)bh * WW * CC;
    for (int i = threadIdx.x; i < WW * CC; i += blockDim.x) {
        int w = i / CC, c = i % CC;
        dst[i] = tile[c][w];
    }
}

// ---------------- weight repack ----------------
__global__ void k_repack(const float* __restrict__ w_off, const float* __restrict__ w_dc) {
    int i = blockIdx.x * blockDim.x + threadIdx.x;
    if (i < TT * CC * KK) {
        int t = i / (CC * KK);
        int r = i % (CC * KK);
        int c = r / KK;
        int tap = r % KK;
        g_woff[((tap * 16 + (c >> 2)) * TT + t) * 4 + (c & 3)] = w_off[i];
    }
    if (i < OO * CC * KK) {
        int o = i / (CC * KK);
        int r = i % (CC * KK);
        int c = r / KK;
        int k = r % KK;
        g_wdc[(k * CC + c) * OO + o] = w_dc[i];
    }
}

// ---------------- offset conv: stage-then-GEMM ----------------
#define OFF_SMEM_BYTES ((CC*SAS + KK*16*TT*4) * 4)
__global__ void __launch_bounds__(256, 1) k_offconv(const float* __restrict__ b_off) {
    extern __shared__ float sm[];
    float* sX  = sm;                 // CC * SAS
    float* sWo = sm + CC * SAS;      // 9*1152

    int tid = threadIdx.x;
    int pix0 = blockIdx.x * TPX;
    int b = pix0 / HWIMG;
    int ip0 = pix0 % HWIMG;
    const float* xb = g_xn + (size_t)b * HWIMG * CC;

    for (int i = tid; i < KK * 16 * TT; i += 256)
        ((float4*)sWo)[i] = ((const float4*)g_woff)[i];

    float acc[TT];
#pragma unroll
    for (int t = 0; t < TT; t++) acc[t] = b_off[t];

#pragma unroll 1
    for (int tap = 0; tap < KK; tap++) {
        int dy = tap / 3 - 1, dx = tap % 3 - 1;
        __syncthreads();
        // stage shifted rows: 64 px per iter, lanes = 8 px x 4 chunk-quads
#pragma unroll 1
        for (int it = 0; it < 4; it++) {
            int p = it * 64 + (tid >> 2);
            int c2 = tid & 3;
            int ip = ip0 + p;
            int h = ip / WW, w = ip % WW;
            int y = h + dy, x = w + dx;
            float vm = ((unsigned)y < HH && (unsigned)x < WW) ? 1.f : 0.f;
            int yc = min(max(y, 0), HH - 1), xc = min(max(x, 0), WW - 1);
            const float4* src = (const float4*)(xb + (size_t)(yc * WW + xc) * CC) + c2;
#pragma unroll
            for (int q = 0; q < 4; q++) {
                float4 v = src[4 * q];
                int ch = (c2 + 4 * q) * 4;
                sX[(ch + 0) * SAS + p] = v.x * vm;
                sX[(ch + 1) * SAS + p] = v.y * vm;
                sX[(ch + 2) * SAS + p] = v.z * vm;
                sX[(ch + 3) * SAS + p] = v.w * vm;
            }
        }
        __syncthreads();
        const float4* wr = (const float4*)(sWo + tap * 16 * TT * 4);
#pragma unroll 4
        for (int c4 = 0; c4 < 16; c4++) {
            float x0 = sX[(c4 * 4 + 0) * SAS + tid];
            float x1 = sX[(c4 * 4 + 1) * SAS + tid];
            float x2 = sX[(c4 * 4 + 2) * SAS + tid];
            float x3 = sX[(c4 * 4 + 3) * SAS + tid];
#pragma unroll
            for (int t = 0; t < TT; t++) {
                float4 wv = wr[c4 * TT + t];
                acc[t] += x0 * wv.x + x1 * wv.y + x2 * wv.z + x3 * wv.w;
            }
        }
    }
    // smem bounce for coalesced store
    __syncthreads();
#pragma unroll
    for (int t = 0; t < TT; t++) sX[tid * TT + t] = acc[t];
    __syncthreads();
    float4* dst = (float4*)(g_offs + (size_t)pix0 * TT);
    for (int i = tid; i < TPX * TT / 4; i += 256)
        dst[i] = ((const float4*)sX)[i];
}

// ---------------- main fused gather + register-blocked GEMM ----------------
#define MAIN_SMEM_BYTES ((2*CC*SAS + 2*CC*OO + TPX*TT + TPX*8) * 4)
__global__ void __launch_bounds__(256, 1) k_main(const float* __restrict__ b_dc,
                                                 float* __restrict__ out) {
    extern __shared__ float sm[];
    float* sA   = sm;                      // 2 * 64 * SAS
    float* sW   = sA + 2 * CC * SAS;       // 2 * 64 * 64
    float* sOff = sW + 2 * CC * OO;        // 256 * 18
    float* sP   = sOff + TPX * TT;         // 256 * 8

    int tid = threadIdx.x;
    int pix0 = blockIdx.x * TPX;
    int b = pix0 / HWIMG;
    int ip0 = pix0 % HWIMG;
    const float* xb = g_xn + (size_t)b * HWIMG * CC;

    // load offsets for the tile
    {
        const float4* src = (const float4*)(g_offs + (size_t)pix0 * TT);
        for (int i = tid; i < TPX * TT / 4; i += 256) ((float4*)sOff)[i] = src[i];
    }
    // stage weights for k=0
    for (int i = tid; i < CC * OO / 4; i += 256)
        ((float4*)sW)[i] = ((const float4*)g_wdc)[i];

    int myh = (ip0 + tid) / WW;
    int myw = (ip0 + tid) % WW;

    float acc[8][8];
#pragma unroll
    for (int j = 0; j < 8; j++) {
        float bv = b_dc[(tid & 7) * 8 + j];
#pragma unroll
        for (int i2 = 0; i2 < 8; i2++) acc[j][i2] = bv;
    }

#define PARAMS(KI) do {                                                        \
        float dy = sOff[tid * TT + 2 * (KI)];                                  \
        float dx = sOff[tid * TT + 2 * (KI) + 1];                              \
        float py = (float)(myh + (KI) / 3 - 1) + dy;                           \
        float px = (float)(myw + (KI) % 3 - 1) + dx;                           \
        float y0f = floorf(py), x0f = floorf(px);                              \
        float ly = py - y0f, lx = px - x0f;                                    \
        int y0 = (int)y0f, x0 = (int)x0f;                                      \
        int y1 = y0 + 1, x1 = x0 + 1;                                          \
        float w00 = (1.f - ly) * (1.f - lx), w01 = (1.f - ly) * lx;            \
        float w10 = ly * (1.f - lx), w11 = ly * lx;                            \
        bool vy0 = (unsigned)y0 < HH, vy1 = (unsigned)y1 < HH;                 \
        bool vx0 = (unsigned)x0 < WW, vx1 = (unsigned)x1 < WW;                 \
        w00 *= (float)(vy0 && vx0); w01 *= (float)(vy0 && vx1);                \
        w10 *= (float)(vy1 && vx0); w11 *= (float)(vy1 && vx1);                \
        int yc0 = min(max(y0, 0), HH - 1), yc1 = min(max(y1, 0), HH - 1);      \
        int xc0 = min(max(x0, 0), WW - 1), xc1 = min(max(x1, 0), WW - 1);      \
        float* pp = sP + tid * 8;                                              \
        pp[0] = w00; pp[1] = w01; pp[2] = w10; pp[3] = w11;                    \
        pp[4] = __int_as_float((yc0 * WW + xc0) * CC);                         \
        pp[5] = __int_as_float((yc0 * WW + xc1) * CC);                         \
        pp[6] = __int_as_float((yc1 * WW + xc0) * CC);                         \
        pp[7] = __int_as_float((yc1 * WW + xc1) * CC);                         \
    } while (0)

#define GATHER(BUF) do {                                                       \
        float* sAb = sA + (BUF) * (CC * SAS);                                  \
        _Pragma("unroll 1")                                                    \
        for (int it = 0; it < 4; it++) {                                       \
            int p = it * 64 + (tid >> 2);                                      \
            int c2 = tid & 3;                                                  \
            const float* pp = sP + p * 8;                                      \
            float w00 = pp[0], w01 = pp[1], w10 = pp[2], w11 = pp[3];          \
            const float4* r00 = (const float4*)(xb + __float_as_int(pp[4])) + c2; \
            const float4* r01 = (const float4*)(xb + __float_as_int(pp[5])) + c2; \
            const float4* r10 = (const float4*)(xb + __float_as_int(pp[6])) + c2; \
            const float4* r11 = (const float4*)(xb + __float_as_int(pp[7])) + c2; \
            _Pragma("unroll")                                                  \
            for (int q = 0; q < 4; q++) {                                      \
                float4 a = r00[4 * q], b2 = r01[4 * q];                        \
                float4 c3 = r10[4 * q], d = r11[4 * q];                        \
                int ch = (c2 + 4 * q) * 4;                                     \
                sAb[(ch + 0) * SAS + p] = w00 * a.x + w01 * b2.x + w10 * c3.x + w11 * d.x; \
                sAb[(ch + 1) * SAS + p] = w00 * a.y + w01 * b2.y + w10 * c3.y + w11 * d.y; \
                sAb[(ch + 2) * SAS + p] = w00 * a.z + w01 * b2.z + w10 * c3.z + w11 * d.z; \
                sAb[(ch + 3) * SAS + p] = w00 * a.w + w01 * b2.w + w10 * c3.w + w11 * d.w; \
            }                                                                  \
        }                                                                      \
    } while (0)

    PARAMS(0);
    __syncthreads();
    GATHER(0);

#pragma unroll 1
    for (int k = 0; k < KK; k++) {
        __syncthreads();
        if (k < KK - 1) {
            const float4* srcw = (const float4*)(g_wdc + (size_t)(k + 1) * CC * OO);
            float4* dstw = (float4*)(sW + ((k + 1) & 1) * CC * OO);
            for (int i = tid; i < CC * OO / 4; i += 256) dstw[i] = srcw[i];
            PARAMS(k + 1);
            __syncthreads();
            GATHER((k + 1) & 1);
        }
        // ---- register-blocked GEMM: 8 pixels x 8 outputs ----
        {
            const float* A = sA + (k & 1) * (CC * SAS) + (tid >> 3) * 8;
            const float* W = sW + (k & 1) * (CC * OO) + (tid & 7) * 8;
#pragma unroll 8
            for (int c = 0; c < CC; c++) {
                float4 a0 = *(const float4*)(A + c * SAS);
                float4 a1 = *(const float4*)(A + c * SAS + 4);
                float4 w0 = *(const float4*)(W + c * OO);
                float4 w1 = *(const float4*)(W + c * OO + 4);
                float av[8] = {a0.x, a0.y, a0.z, a0.w, a1.x, a1.y, a1.z, a1.w};
                float wv[8] = {w0.x, w0.y, w0.z, w0.w, w1.x, w1.y, w1.z, w1.w};
#pragma unroll
                for (int j = 0; j < 8; j++)
#pragma unroll
                    for (int i2 = 0; i2 < 8; i2++)
                        acc[j][i2] += wv[j] * av[i2];
            }
        }
    }

    // ---- epilogue: stage transposed, write coalesced NCHW ----
    __syncthreads();
    float* oT = sA;   // 64 rows x SAS
    {
        int pg = tid >> 3, og = tid & 7;
#pragma unroll
        for (int j = 0; j < 8; j++) {
#pragma unroll
            for (int qq = 0; qq < 2; qq++) {
                float4 v = make_float4(acc[j][qq * 4], acc[j][qq * 4 + 1],
                                       acc[j][qq * 4 + 2], acc[j][qq * 4 + 3]);
                *(float4*)(oT + (og * 8 + j) * SAS + pg * 8 + qq * 4) = v;
            }
        }
    }
    __syncthreads();
    {
        size_t obase = (size_t)b * OO * HWIMG + ip0;
        for (int i = tid; i < OO * (TPX / 4); i += 256) {
            int o = i >> 6;          // 64 float4 per output row
            int pq = i & 63;
            float4 v = *(const float4*)(oT + o * SAS + pq * 4);
            *(float4*)(out + obase + (size_t)o * HWIMG + pq * 4) = v;
        }
    }
#undef PARAMS
#undef GATHER
}

// ---------------- launch ----------------
extern "C" void kernel_launch(void* const* d_in, const int* in_sizes, int n_in,
                              void* d_out, int out_size) {
    const float* x     = (const float*)d_in[0];
    const float* w_off = (const float*)d_in[1];
    const float* b_off = (const float*)d_in[2];
    const float* w_dc  = (const float*)d_in[3];
    const float* b_dc  = (const float*)d_in[4];
    float* out = (float*)d_out;

    cudaFuncSetAttribute(k_main, cudaFuncAttributeMaxDynamicSharedMemorySize, MAIN_SMEM_BYTES);
    cudaFuncSetAttribute(k_offconv, cudaFuncAttributeMaxDynamicSharedMemorySize, OFF_SMEM_BYTES);

    k_transpose<<<BB * HH, 256>>>(x);
    k_repack<<<(OO * CC * KK + 255) / 256, 256>>>(w_off, w_dc);
    k_offconv<<<NTILE, 256, OFF_SMEM_BYTES>>>(b_off);
    k_main<<<NTILE, 256, MAIN_SMEM_BYTES>>>(b_dc, out);
}

// round 4
// speedup vs baseline: 2.9342x; 1.0291x over previous
#include <cuda_runtime.h>
#include <cuda_bf16.h>
#include <cstdint>

#define BB 4
#define CC 64
#define HH 96
#define WW 96
#define TT 18
#define KK 9
#define OO 64
#define HWIMG (HH*WW)          // 9216
#define NPIX (BB*HWIMG)        // 36864
#define MT 128                 // pixels per tile
#define NTIL (NPIX/MT)         // 288

// -------- scratch (device globals) --------
__device__ float g_xn[NPIX * CC];                    // NHWC x
__device__ float g_offs[NPIX * TT];                  // [pix][18]
__device__ uint4 g_wdc4[(KK * 2 * OO * CC) / 8];     // bf16 swizzled [k][term][o:64][c:64]
__device__ uint4 g_woff4[(KK * 2 * 32 * CC) / 8];    // bf16 swizzled [k][term][o:32][c:64]

// ---------------- helpers ----------------
__device__ __forceinline__ uint32_t smem_u32(const void* p) {
    uint32_t a;
    asm("{ .reg .u64 t; cvta.to.shared.u64 t, %1; cvt.u32.u64 %0, t; }" : "=r"(a) : "l"(p));
    return a;
}
#define SWZ(b) ((b) ^ (((b) >> 3) & 0x70))

__device__ __forceinline__ uint32_t pack_bf16(float a, float b) {
    __nv_bfloat162 t = __floats2bfloat162_rn(a, b);   // .x=a (low half)
    return *(uint32_t*)&t;
}
#define STS128(a, r0, r1, r2, r3) asm volatile("st.shared.v4.b32 [%0], {%1,%2,%3,%4};" :: "r"(a), "r"(r0), "r"(r1), "r"(r2), "r"(r3) : "memory")

__device__ __forceinline__ void ldm4(uint32_t* r, uint32_t addr) {
    asm volatile("ldmatrix.sync.aligned.m8n8.x4.shared.b16 {%0,%1,%2,%3}, [%4];"
                 : "=r"(r[0]), "=r"(r[1]), "=r"(r[2]), "=r"(r[3]) : "r"(addr));
}
__device__ __forceinline__ void mma_bf16(float* c, const uint32_t* a, uint32_t b0, uint32_t b1) {
    asm volatile(
        "mma.sync.aligned.m16n8k16.row.col.f32.bf16.bf16.f32 "
        "{%0,%1,%2,%3}, {%4,%5,%6,%7}, {%8,%9}, {%0,%1,%2,%3};"
        : "+f"(c[0]), "+f"(c[1]), "+f"(c[2]), "+f"(c[3])
        : "r"(a[0]), "r"(a[1]), "r"(a[2]), "r"(a[3]), "r"(b0), "r"(b1));
}

// ---------------- NCHW -> NHWC transpose ----------------
__global__ void k_transpose(const float* __restrict__ x) {
    __shared__ float tile[64][97];
    int bh = blockIdx.x;
    int b = bh / HH;
    const float* src = x + ((size_t)b * CC) * HWIMG + (size_t)(bh % HH) * WW;
    for (int i = threadIdx.x; i < CC * WW; i += blockDim.x) {
        int c = i / WW, w = i % WW;
        tile[c][w] = src[(size_t)c * HWIMG + w];
    }
    __syncthreads();
    float* dst = g_xn + (size_t)bh * WW * CC;
    for (int i = threadIdx.x; i < WW * CC; i += blockDim.x) {
        int w = i / CC, c = i % CC;
        dst[i] = tile[c][w];
    }
}

// ---------------- weight repack: split bf16 hi/lo, pre-swizzled [o][c] rows ----------------
__global__ void k_repack(const float* __restrict__ w_off, const float* __restrict__ w_dc) {
    int i = blockIdx.x * blockDim.x + threadIdx.x;
    if (i < OO * CC * KK) {
        int o = i / (CC * KK);
        int r = i % (CC * KK);
        int c = r / KK;
        int k = r % KK;
        float v = w_dc[i];
        __nv_bfloat16 hi = __float2bfloat16(v);
        __nv_bfloat16 lo = __float2bfloat16(v - __bfloat162float(hi));
        uint32_t sw = SWZ((uint32_t)(o * 128 + c * 2));
        __nv_bfloat16* base = (__nv_bfloat16*)g_wdc4;
        base[(size_t)(k * 2 + 0) * 4096 + (sw >> 1)] = hi;
        base[(size_t)(k * 2 + 1) * 4096 + (sw >> 1)] = lo;
    }
    if (i < 32 * CC * KK) {
        int o = i / (CC * KK);
        int r = i % (CC * KK);
        int c = r / KK;
        int k = r % KK;
        float v = (o < TT) ? w_off[(size_t)o * CC * KK + c * KK + k] : 0.f;
        __nv_bfloat16 hi = __float2bfloat16(v);
        __nv_bfloat16 lo = __float2bfloat16(v - __bfloat162float(hi));
        uint32_t sw = SWZ((uint32_t)(o * 128 + c * 2));
        __nv_bfloat16* base = (__nv_bfloat16*)g_woff4;
        base[(size_t)(k * 2 + 0) * 2048 + (sw >> 1)] = hi;
        base[(size_t)(k * 2 + 1) * 2048 + (sw >> 1)] = lo;
    }
}

// fragment address helpers (SW128-swizzled 128B rows)
__device__ __forceinline__ uint32_t a_frag_addr(uint32_t base, int row0, int kt, int lane) {
    int rowoff = ((lane >> 3) & 1) * 8 + (lane & 7);
    int seg = kt * 2 + (lane >> 4);
    return base + SWZ((uint32_t)((row0 + rowoff) * 128 + seg * 16));
}
__device__ __forceinline__ uint32_t b_frag_addr(uint32_t base, int n0p, int kt, int lane) {
    int rowoff = ((lane >> 4) & 1) * 8 + (lane & 7);
    int seg = kt * 2 + ((lane >> 3) & 1);
    return base + SWZ((uint32_t)((n0p + rowoff) * 128 + seg * 16));
}

// ============== main deformable conv: gather + mma.sync ==============
// smem: A 4x16KB (buf,term) = 65536 | W 2x16KB (buf; hi+lo) = 32768
#define MAIN_SW   65536
#define MAIN_SMEM (MAIN_SW + 32768)

__global__ void __launch_bounds__(256, 2) k_main_m(const float* __restrict__ b_dc,
                                                   float* __restrict__ out) {
    extern __shared__ __align__(1024) char smem[];
    uint32_t sb = smem_u32(smem);

    int tid = threadIdx.x;
    int wid = tid >> 5, lane = tid & 31;
    int wm = wid & 3, wn = wid >> 2;
    int m0 = wm * 32, n0 = wn * 32;

    int pix0 = blockIdx.x * MT;
    int b = pix0 / HWIMG, ip0 = pix0 % HWIMG;
    const float* xb = g_xn + (size_t)b * HWIMG * CC;
    int px = tid >> 1, c0 = (tid & 1) * 32;
    int ip = ip0 + px, myh = ip / WW, myw = ip % WW;
    const float* offp = g_offs + (size_t)(pix0 + px) * TT;

    float acc[2][4][4];
#pragma unroll
    for (int nt = 0; nt < 4; nt++) {
        int o = n0 + nt * 8 + (lane & 3) * 2;
        float b0v = b_dc[o], b1v = b_dc[o + 1];
#pragma unroll
        for (int mt = 0; mt < 2; mt++) {
            acc[mt][nt][0] = b0v; acc[mt][nt][1] = b1v;
            acc[mt][nt][2] = b0v; acc[mt][nt][3] = b1v;
        }
    }

#define GATHER(KI, BUF) do {                                                       \
        float dy = offp[2 * (KI)], dx = offp[2 * (KI) + 1];                        \
        float py = (float)(myh + (KI) / 3 - 1) + dy;                               \
        float pxx = (float)(myw + (KI) % 3 - 1) + dx;                              \
        float y0f = floorf(py), x0f = floorf(pxx);                                 \
        float ly = py - y0f, lx = pxx - x0f;                                       \
        int y0 = (int)y0f, x0 = (int)x0f, y1 = y0 + 1, x1 = x0 + 1;                \
        float w00 = (1.f - ly) * (1.f - lx), w01 = (1.f - ly) * lx;                \
        float w10 = ly * (1.f - lx), w11 = ly * lx;                                \
        bool vy0 = (unsigned)y0 < HH, vy1 = (unsigned)y1 < HH;                     \
        bool vx0 = (unsigned)x0 < WW, vx1 = (unsigned)x1 < WW;                     \
        w00 *= (float)(vy0 && vx0); w01 *= (float)(vy0 && vx1);                    \
        w10 *= (float)(vy1 && vx0); w11 *= (float)(vy1 && vx1);                    \
        int yc0 = min(max(y0, 0), HH - 1), yc1 = min(max(y1, 0), HH - 1);          \
        int xc0 = min(max(x0, 0), WW - 1), xc1 = min(max(x1, 0), WW - 1);          \
        const float4* r00 = (const float4*)(xb + (size_t)(yc0 * WW + xc0) * CC) + (c0 >> 2); \
        const float4* r01 = (const float4*)(xb + (size_t)(yc0 * WW + xc1) * CC) + (c0 >> 2); \
        const float4* r10 = (const float4*)(xb + (size_t)(yc1 * WW + xc0) * CC) + (c0 >> 2); \
        const float4* r11 = (const float4*)(xb + (size_t)(yc1 * WW + xc1) * CC) + (c0 >> 2); \
        uint32_t abase_h = sb + ((BUF) * 2 + 0) * 16384;                           \
        uint32_t abase_l = sb + ((BUF) * 2 + 1) * 16384;                           \
        _Pragma("unroll")                                                          \
        for (int q = 0; q < 4; q++) {                                              \
            float4 a0 = r00[2 * q], a1 = r00[2 * q + 1];                           \
            float4 b0 = r01[2 * q], b1 = r01[2 * q + 1];                           \
            float4 c2 = r10[2 * q], c3 = r10[2 * q + 1];                           \
            float4 d0 = r11[2 * q], d1 = r11[2 * q + 1];                           \
            float s[8];                                                            \
            s[0] = w00 * a0.x + w01 * b0.x + w10 * c2.x + w11 * d0.x;              \
            s[1] = w00 * a0.y + w01 * b0.y + w10 * c2.y + w11 * d0.y;              \
            s[2] = w00 * a0.z + w01 * b0.z + w10 * c2.z + w11 * d0.z;              \
            s[3] = w00 * a0.w + w01 * b0.w + w10 * c2.w + w11 * d0.w;              \
            s[4] = w00 * a1.x + w01 * b1.x + w10 * c3.x + w11 * d1.x;              \
            s[5] = w00 * a1.y + w01 * b1.y + w10 * c3.y + w11 * d1.y;              \
            s[6] = w00 * a1.z + w01 * b1.z + w10 * c3.z + w11 * d1.z;              \
            s[7] = w00 * a1.w + w01 * b1.w + w10 * c3.w + w11 * d1.w;              \
            uint32_t hi[4], lo[4];                                                 \
            _Pragma("unroll")                                                      \
            for (int j = 0; j < 4; j++) {                                          \
                float u0 = s[2 * j], u1 = s[2 * j + 1];                            \
                float h0 = __bfloat162float(__float2bfloat16(u0));                 \
                float h1 = __bfloat162float(__float2bfloat16(u1));                 \
                hi[j] = pack_bf16(u0, u1);                                         \
                lo[j] = pack_bf16(u0 - h0, u1 - h1);                               \
            }                                                                      \
            uint32_t sw = SWZ((uint32_t)(px * 128 + (c0 + q * 8) * 2));            \
            STS128(abase_h + sw, hi[0], hi[1], hi[2], hi[3]);                      \
            STS128(abase_l + sw, lo[0], lo[1], lo[2], lo[3]);                      \
        }                                                                          \
    } while (0)

#define WCOPY(KI, BUF) do {                                                        \
        const uint4* srcw = g_wdc4 + (size_t)(KI) * 1024;                          \
        uint4* dstw = (uint4*)(smem + MAIN_SW + (BUF) * 16384);                    \
        for (int i = tid; i < 1024; i += 256) dstw[i] = srcw[i];                   \
    } while (0)

    GATHER(0, 0);
    WCOPY(0, 0);
    __syncthreads();

#pragma unroll 1
    for (int k = 0; k < KK; k++) {
        int buf = k & 1;
        uint32_t abH = sb + (buf * 2 + 0) * 16384;
        uint32_t abL = sb + (buf * 2 + 1) * 16384;
        uint32_t wbH = sb + MAIN_SW + buf * 16384;
        uint32_t wbL = wbH + 8192;
#pragma unroll
        for (int kt = 0; kt < 4; kt++) {
            uint32_t aH[2][4], aL[2][4], bH[2][4], bL[2][4];
#pragma unroll
            for (int mt = 0; mt < 2; mt++) {
                ldm4(aH[mt], a_frag_addr(abH, m0 + mt * 16, kt, lane));
                ldm4(aL[mt], a_frag_addr(abL, m0 + mt * 16, kt, lane));
            }
#pragma unroll
            for (int ntp = 0; ntp < 2; ntp++) {
                ldm4(bH[ntp], b_frag_addr(wbH, n0 + ntp * 16, kt, lane));
                ldm4(bL[ntp], b_frag_addr(wbL, n0 + ntp * 16, kt, lane));
            }
#pragma unroll
            for (int mt = 0; mt < 2; mt++)
#pragma unroll
                for (int nt = 0; nt < 4; nt++) {
                    int ntp = nt >> 1, hi2 = (nt & 1) * 2;
                    mma_bf16(acc[mt][nt], aH[mt], bH[ntp][hi2], bH[ntp][hi2 + 1]);
                    mma_bf16(acc[mt][nt], aH[mt], bL[ntp][hi2], bL[ntp][hi2 + 1]);
                    mma_bf16(acc[mt][nt], aL[mt], bH[ntp][hi2], bH[ntp][hi2 + 1]);
                }
        }
        if (k < KK - 1) {
            GATHER(k + 1, buf ^ 1);
            WCOPY(k + 1, buf ^ 1);
        }
        __syncthreads();
    }

    // epilogue: transpose via smem, coalesced NCHW float4 stores
    float* oT = (float*)smem;   // [64][132]
#pragma unroll
    for (int mt = 0; mt < 2; mt++)
#pragma unroll
        for (int nt = 0; nt < 4; nt++) {
            int o = n0 + nt * 8 + (lane & 3) * 2;
            int p = m0 + mt * 16 + (lane >> 2);
            oT[o * 132 + p]           = acc[mt][nt][0];
            oT[(o + 1) * 132 + p]     = acc[mt][nt][1];
            oT[o * 132 + p + 8]       = acc[mt][nt][2];
            oT[(o + 1) * 132 + p + 8] = acc[mt][nt][3];
        }
    __syncthreads();
    {
        size_t obase = (size_t)b * OO * HWIMG + ip0;
        for (int i = tid; i < OO * (MT / 4); i += 256) {
            int o = i >> 5, p4 = i & 31;
            float4 v = *(const float4*)(oT + o * 132 + p4 * 4);
            *(float4*)(out + obase + (size_t)o * HWIMG + p4 * 4) = v;
        }
    }
#undef GATHER
#undef WCOPY
}

// ============== offset conv: shift + mma.sync (N=32, 18 real) ==============
#define OFF_SW   65536
#define OFF_SMEM (OFF_SW + 16384)

__global__ void __launch_bounds__(256, 2) k_off_m(const float* __restrict__ b_off) {
    extern __shared__ __align__(1024) char smem[];
    uint32_t sb = smem_u32(smem);

    int tid = threadIdx.x;
    int wid = tid >> 5, lane = tid & 31;
    int m0 = wid * 16;

    int pix0 = blockIdx.x * MT;
    int b = pix0 / HWIMG, ip0 = pix0 % HWIMG;
    const float* xb = g_xn + (size_t)b * HWIMG * CC;
    int px = tid >> 1, c0 = (tid & 1) * 32;
    int ip = ip0 + px, myh = ip / WW, myw = ip % WW;

    float acc[4][4];
#pragma unroll
    for (int nt = 0; nt < 4; nt++) {
        int o = nt * 8 + (lane & 3) * 2;
        float b0v = (o < TT) ? b_off[o] : 0.f;
        float b1v = (o + 1 < TT) ? b_off[o + 1] : 0.f;
        acc[nt][0] = b0v; acc[nt][1] = b1v;
        acc[nt][2] = b0v; acc[nt][3] = b1v;
    }

#define GATHS(KI, BUF) do {                                                        \
        int y = myh + (KI) / 3 - 1, x = myw + (KI) % 3 - 1;                        \
        float vm = ((unsigned)y < HH && (unsigned)x < WW) ? 1.f : 0.f;             \
        int yc = min(max(y, 0), HH - 1), xc = min(max(x, 0), WW - 1);              \
        const float4* r = (const float4*)(xb + (size_t)(yc * WW + xc) * CC) + (c0 >> 2); \
        uint32_t abase_h = sb + ((BUF) * 2 + 0) * 16384;                           \
        uint32_t abase_l = sb + ((BUF) * 2 + 1) * 16384;                           \
        _Pragma("unroll")                                                          \
        for (int q = 0; q < 4; q++) {                                              \
            float4 v0 = r[2 * q], v1 = r[2 * q + 1];                               \
            float s[8] = {v0.x * vm, v0.y * vm, v0.z * vm, v0.w * vm,              \
                          v1.x * vm, v1.y * vm, v1.z * vm, v1.w * vm};             \
            uint32_t hi[4], lo[4];                                                 \
            _Pragma("unroll")                                                      \
            for (int j = 0; j < 4; j++) {                                          \
                float u0 = s[2 * j], u1 = s[2 * j + 1];                            \
                float h0 = __bfloat162float(__float2bfloat16(u0));                 \
                float h1 = __bfloat162float(__float2bfloat16(u1));                 \
                hi[j] = pack_bf16(u0, u1);                                         \
                lo[j] = pack_bf16(u0 - h0, u1 - h1);                               \
            }                                                                      \
            uint32_t sw = SWZ((uint32_t)(px * 128 + (c0 + q * 8) * 2));            \
            STS128(abase_h + sw, hi[0], hi[1], hi[2], hi[3]);                      \
            STS128(abase_l + sw, lo[0], lo[1], lo[2], lo[3]);                      \
        }                                                                          \
    } while (0)

#define WCOPYO(KI, BUF) do {                                                       \
        const uint4* srcw = g_woff4 + (size_t)(KI) * 512;                          \
        uint4* dstw = (uint4*)(smem + OFF_SW + (BUF) * 8192);                      \
        for (int i = tid; i < 512; i += 256) dstw[i] = srcw[i];                    \
    } while (0)

    GATHS(0, 0);
    WCOPYO(0, 0);
    __syncthreads();

#pragma unroll 1
    for (int k = 0; k < KK; k++) {
        int buf = k & 1;
        uint32_t abH = sb + (buf * 2 + 0) * 16384;
        uint32_t abL = sb + (buf * 2 + 1) * 16384;
        uint32_t wbH = sb + OFF_SW + buf * 8192;
        uint32_t wbL = wbH + 4096;
#pragma unroll
        for (int kt = 0; kt < 4; kt++) {
            uint32_t aH[4], aL[4], bH[2][4], bL[2][4];
            ldm4(aH, a_frag_addr(abH, m0, kt, lane));
            ldm4(aL, a_frag_addr(abL, m0, kt, lane));
#pragma unroll
            for (int ntp = 0; ntp < 2; ntp++) {
                ldm4(bH[ntp], b_frag_addr(wbH, ntp * 16, kt, lane));
                ldm4(bL[ntp], b_frag_addr(wbL, ntp * 16, kt, lane));
            }
#pragma unroll
            for (int nt = 0; nt < 4; nt++) {
                int ntp = nt >> 1, hi2 = (nt & 1) * 2;
                mma_bf16(acc[nt], aH, bH[ntp][hi2], bH[ntp][hi2 + 1]);
                mma_bf16(acc[nt], aH, bL[ntp][hi2], bL[ntp][hi2 + 1]);
                mma_bf16(acc[nt], aL, bH[ntp][hi2], bH[ntp][hi2 + 1]);
            }
        }
        if (k < KK - 1) {
            GATHS(k + 1, buf ^ 1);
            WCOPYO(k + 1, buf ^ 1);
        }
        __syncthreads();
    }

    // epilogue: oT[p][o] stride 20, then pack to g_offs[pix][18]
    float* oT = (float*)smem;   // [128][20]
#pragma unroll
    for (int nt = 0; nt < 4; nt++) {
        int o = nt * 8 + (lane & 3) * 2;
        int p = m0 + (lane >> 2);
        if (o < TT) {
            oT[p * 20 + o] = acc[nt][0];
            oT[(p + 8) * 20 + o] = acc[nt][2];
        }
        if (o + 1 < TT) {
            oT[p * 20 + o + 1] = acc[nt][1];
            oT[(p + 8) * 20 + o + 1] = acc[nt][3];
        }
    }
    __syncthreads();
    {
        float* dst = g_offs + (size_t)pix0 * TT;
        for (int i = tid; i < MT * TT; i += 256)
            dst[i] = oT[(i / TT) * 20 + (i % TT)];
    }
#undef GATHS
#undef WCOPYO
}

// ---------------- launch ----------------
extern "C" void kernel_launch(void* const* d_in, const int* in_sizes, int n_in,
                              void* d_out, int out_size) {
    const float* x     = (const float*)d_in[0];
    const float* w_off = (const float*)d_in[1];
    const float* b_off = (const float*)d_in[2];
    const float* w_dc  = (const float*)d_in[3];
    const float* b_dc  = (const float*)d_in[4];
    float* out = (float*)d_out;

    cudaFuncSetAttribute(k_off_m, cudaFuncAttributeMaxDynamicSharedMemorySize, OFF_SMEM);
    cudaFuncSetAttribute(k_main_m, cudaFuncAttributeMaxDynamicSharedMemorySize, MAIN_SMEM);

    k_transpose<<<BB * HH, 256>>>(x);
    k_repack<<<(OO * CC * KK + 255) / 256, 256>>>(w_off, w_dc);
    k_off_m<<<NTIL, 256, OFF_SMEM>>>(b_off);
    k_main_m<<<NTIL, 256, MAIN_SMEM>>>(b_dc, out);
}

// round 5
// speedup vs baseline: 4.9834x; 1.6984x over previous
#include <cuda_runtime.h>
#include <cuda_bf16.h>
#include <cstdint>

#define BB 4
#define CC 64
#define HH 96
#define WW 96
#define TT 18
#define KK 9
#define OO 64
#define HWIMG (HH*WW)          // 9216
#define NPIX (BB*HWIMG)        // 36864
#define MT 128                 // pixels per tile
#define NTIL (NPIX/MT)         // 288

// -------- scratch (device globals) --------
__device__ float g_xn[NPIX * CC];                    // NHWC x
__device__ float g_offs[NPIX * TT];                  // [pix][18]
__device__ uint4 g_wdc4[(KK * 2 * OO * CC) / 8];     // bf16 swizzled [k][term][o:64][c:64]
__device__ uint4 g_woff4[(KK * 2 * 32 * CC) / 8];    // bf16 swizzled [k][term][o:32][c:64]

// ---------------- helpers ----------------
__device__ __forceinline__ uint32_t smem_u32(const void* p) {
    uint32_t a;
    asm("{ .reg .u64 t; cvta.to.shared.u64 t, %1; cvt.u32.u64 %0, t; }" : "=r"(a) : "l"(p));
    return a;
}
#define SWZ(b) ((b) ^ (((b) >> 3) & 0x70))

__device__ __forceinline__ uint32_t pack_bf16(float a, float b) {
    __nv_bfloat162 t = __floats2bfloat162_rn(a, b);   // .x=a (low half)
    return *(uint32_t*)&t;
}
#define STS64(a, r0, r1) asm volatile("st.shared.v2.b32 [%0], {%1,%2};" :: "r"(a), "r"(r0), "r"(r1) : "memory")

__device__ __forceinline__ void ldm4(uint32_t* r, uint32_t addr) {
    asm volatile("ldmatrix.sync.aligned.m8n8.x4.shared.b16 {%0,%1,%2,%3}, [%4];"
                 : "=r"(r[0]), "=r"(r[1]), "=r"(r[2]), "=r"(r[3]) : "r"(addr));
}
__device__ __forceinline__ void mma_bf16(float* c, const uint32_t* a, uint32_t b0, uint32_t b1) {
    asm volatile(
        "mma.sync.aligned.m16n8k16.row.col.f32.bf16.bf16.f32 "
        "{%0,%1,%2,%3}, {%4,%5,%6,%7}, {%8,%9}, {%0,%1,%2,%3};"
        : "+f"(c[0]), "+f"(c[1]), "+f"(c[2]), "+f"(c[3])
        : "r"(a[0]), "r"(a[1]), "r"(a[2]), "r"(a[3]), "r"(b0), "r"(b1));
}

// ---------------- NCHW -> NHWC transpose ----------------
__global__ void k_transpose(const float* __restrict__ x) {
    __shared__ float tile[64][97];
    int bh = blockIdx.x;
    int b = bh / HH;
    const float* src = x + ((size_t)b * CC) * HWIMG + (size_t)(bh % HH) * WW;
    for (int i = threadIdx.x; i < CC * WW; i += blockDim.x) {
        int c = i / WW, w = i % WW;
        tile[c][w] = src[(size_t)c * HWIMG + w];
    }
    __syncthreads();
    float* dst = g_xn + (size_t)bh * WW * CC;
    for (int i = threadIdx.x; i < WW * CC; i += blockDim.x) {
        int w = i / CC, c = i % CC;
        dst[i] = tile[c][w];
    }
}

// ---------------- weight repack: split bf16 hi/lo, pre-swizzled [o][c] rows ----------------
__global__ void k_repack(const float* __restrict__ w_off, const float* __restrict__ w_dc) {
    int i = blockIdx.x * blockDim.x + threadIdx.x;
    if (i < OO * CC * KK) {
        int o = i / (CC * KK);
        int r = i % (CC * KK);
        int c = r / KK;
        int k = r % KK;
        float v = w_dc[i];
        __nv_bfloat16 hi = __float2bfloat16(v);
        __nv_bfloat16 lo = __float2bfloat16(v - __bfloat162float(hi));
        uint32_t sw = SWZ((uint32_t)(o * 128 + c * 2));
        __nv_bfloat16* base = (__nv_bfloat16*)g_wdc4;
        base[(size_t)(k * 2 + 0) * 4096 + (sw >> 1)] = hi;
        base[(size_t)(k * 2 + 1) * 4096 + (sw >> 1)] = lo;
    }
    if (i < 32 * CC * KK) {
        int o = i / (CC * KK);
        int r = i % (CC * KK);
        int c = r / KK;
        int k = r % KK;
        float v = (o < TT) ? w_off[(size_t)o * CC * KK + c * KK + k] : 0.f;
        __nv_bfloat16 hi = __float2bfloat16(v);
        __nv_bfloat16 lo = __float2bfloat16(v - __bfloat162float(hi));
        uint32_t sw = SWZ((uint32_t)(o * 128 + c * 2));
        __nv_bfloat16* base = (__nv_bfloat16*)g_woff4;
        base[(size_t)(k * 2 + 0) * 2048 + (sw >> 1)] = hi;
        base[(size_t)(k * 2 + 1) * 2048 + (sw >> 1)] = lo;
    }
}

// fragment address helpers (SW128-swizzled 128B rows)
__device__ __forceinline__ uint32_t a_frag_addr(uint32_t base, int row0, int kt, int lane) {
    int rowoff = ((lane >> 3) & 1) * 8 + (lane & 7);
    int seg = kt * 2 + (lane >> 4);
    return base + SWZ((uint32_t)((row0 + rowoff) * 128 + seg * 16));
}
__device__ __forceinline__ uint32_t b_frag_addr(uint32_t base, int n0p, int kt, int lane) {
    int rowoff = ((lane >> 4) & 1) * 8 + (lane & 7);
    int seg = kt * 2 + ((lane >> 3) & 1);
    return base + SWZ((uint32_t)((n0p + rowoff) * 128 + seg * 16));
}

// ============== main deformable conv: coalesced gather + mma.sync ==============
// smem: A 4x16KB (buf,term) = 65536 | W 2x16KB = 32768 | sOff 9216
#define MAIN_SW   65536
#define MAIN_SOFF (MAIN_SW + 32768)
#define MAIN_SMEM (MAIN_SOFF + MT * TT * 4)

__global__ void __launch_bounds__(256, 2) k_main_m(const float* __restrict__ b_dc,
                                                   float* __restrict__ out) {
    extern __shared__ __align__(1024) char smem[];
    uint32_t sb = smem_u32(smem);
    float* sOff = (float*)(smem + MAIN_SOFF);

    int tid = threadIdx.x;
    int wid = tid >> 5, lane = tid & 31;
    int wm = wid & 3, wn = wid >> 2;
    int m0 = wm * 32, n0 = wn * 32;

    int pix0 = blockIdx.x * MT;
    int b = pix0 / HWIMG, ip0 = pix0 % HWIMG;
    const float* xb = g_xn + (size_t)b * HWIMG * CC;
    int lpx = tid >> 4;      // pixel sub-index within pass
    int ck  = tid & 15;      // 16B channel chunk (4 fp32 channels)

    // stage offsets for the tile (128 x 18 floats)
    {
        const float4* srcO = (const float4*)(g_offs + (size_t)pix0 * TT);
        for (int i = tid; i < MT * TT / 4; i += 256) ((float4*)sOff)[i] = srcO[i];
    }

    float acc[2][4][4];
#pragma unroll
    for (int nt = 0; nt < 4; nt++) {
        int o = n0 + nt * 8 + (lane & 3) * 2;
        float b0v = b_dc[o], b1v = b_dc[o + 1];
#pragma unroll
        for (int mt = 0; mt < 2; mt++) {
            acc[mt][nt][0] = b0v; acc[mt][nt][1] = b1v;
            acc[mt][nt][2] = b0v; acc[mt][nt][3] = b1v;
        }
    }

#define GATHER(KI, BUF) do {                                                       \
        uint32_t abase_h = sb + ((BUF) * 2 + 0) * 16384;                           \
        uint32_t abase_l = sb + ((BUF) * 2 + 1) * 16384;                           \
        _Pragma("unroll")                                                          \
        for (int ps = 0; ps < 8; ps++) {                                           \
            int px = ps * 16 + lpx;                                                \
            float dy = sOff[px * TT + 2 * (KI)];                                   \
            float dx = sOff[px * TT + 2 * (KI) + 1];                               \
            int ip = ip0 + px;                                                     \
            int ph = ip / WW, pw = ip - ph * WW;                                   \
            float py = (float)(ph + (KI) / 3 - 1) + dy;                            \
            float pxx = (float)(pw + (KI) % 3 - 1) + dx;                           \
            float y0f = floorf(py), x0f = floorf(pxx);                             \
            float ly = py - y0f, lx = pxx - x0f;                                   \
            int y0 = (int)y0f, x0 = (int)x0f, y1 = y0 + 1, x1 = x0 + 1;            \
            float w00 = (1.f - ly) * (1.f - lx), w01 = (1.f - ly) * lx;            \
            float w10 = ly * (1.f - lx), w11 = ly * lx;                            \
            bool vy0 = (unsigned)y0 < HH, vy1 = (unsigned)y1 < HH;                 \
            bool vx0 = (unsigned)x0 < WW, vx1 = (unsigned)x1 < WW;                 \
            w00 *= (float)(vy0 && vx0); w01 *= (float)(vy0 && vx1);                \
            w10 *= (float)(vy1 && vx0); w11 *= (float)(vy1 && vx1);                \
            int yc0 = min(max(y0, 0), HH - 1), yc1 = min(max(y1, 0), HH - 1);      \
            int xc0 = min(max(x0, 0), WW - 1), xc1 = min(max(x1, 0), WW - 1);      \
            float4 a4 = ((const float4*)(xb + (size_t)(yc0 * WW + xc0) * CC))[ck]; \
            float4 b4 = ((const float4*)(xb + (size_t)(yc0 * WW + xc1) * CC))[ck]; \
            float4 c4 = ((const float4*)(xb + (size_t)(yc1 * WW + xc0) * CC))[ck]; \
            float4 d4 = ((const float4*)(xb + (size_t)(yc1 * WW + xc1) * CC))[ck]; \
            float s0 = w00 * a4.x + w01 * b4.x + w10 * c4.x + w11 * d4.x;          \
            float s1 = w00 * a4.y + w01 * b4.y + w10 * c4.y + w11 * d4.y;          \
            float s2 = w00 * a4.z + w01 * b4.z + w10 * c4.z + w11 * d4.z;          \
            float s3 = w00 * a4.w + w01 * b4.w + w10 * c4.w + w11 * d4.w;          \
            float h0 = __bfloat162float(__float2bfloat16(s0));                     \
            float h1 = __bfloat162float(__float2bfloat16(s1));                     \
            float h2 = __bfloat162float(__float2bfloat16(s2));                     \
            float h3 = __bfloat162float(__float2bfloat16(s3));                     \
            uint32_t hiA = pack_bf16(s0, s1), hiB = pack_bf16(s2, s3);             \
            uint32_t loA = pack_bf16(s0 - h0, s1 - h1), loB = pack_bf16(s2 - h2, s3 - h3); \
            uint32_t swa = SWZ((uint32_t)(px * 128 + (ck >> 1) * 16)) + (ck & 1) * 8; \
            STS64(abase_h + swa, hiA, hiB);                                        \
            STS64(abase_l + swa, loA, loB);                                        \
        }                                                                          \
    } while (0)

#define WCOPY(KI, BUF) do {                                                        \
        const uint4* srcw = g_wdc4 + (size_t)(KI) * 1024;                          \
        uint4* dstw = (uint4*)(smem + MAIN_SW + (BUF) * 16384);                    \
        for (int i = tid; i < 1024; i += 256) dstw[i] = srcw[i];                   \
    } while (0)

    __syncthreads();   // sOff ready
    GATHER(0, 0);
    WCOPY(0, 0);
    __syncthreads();

#pragma unroll 1
    for (int k = 0; k < KK; k++) {
        int buf = k & 1;
        uint32_t abH = sb + (buf * 2 + 0) * 16384;
        uint32_t abL = sb + (buf * 2 + 1) * 16384;
        uint32_t wbH = sb + MAIN_SW + buf * 16384;
        uint32_t wbL = wbH + 8192;
#pragma unroll
        for (int kt = 0; kt < 4; kt++) {
            uint32_t aH[2][4], aL[2][4], bH[2][4], bL[2][4];
#pragma unroll
            for (int mt = 0; mt < 2; mt++) {
                ldm4(aH[mt], a_frag_addr(abH, m0 + mt * 16, kt, lane));
                ldm4(aL[mt], a_frag_addr(abL, m0 + mt * 16, kt, lane));
            }
#pragma unroll
            for (int ntp = 0; ntp < 2; ntp++) {
                ldm4(bH[ntp], b_frag_addr(wbH, n0 + ntp * 16, kt, lane));
                ldm4(bL[ntp], b_frag_addr(wbL, n0 + ntp * 16, kt, lane));
            }
#pragma unroll
            for (int mt = 0; mt < 2; mt++)
#pragma unroll
                for (int nt = 0; nt < 4; nt++) {
                    int ntp = nt >> 1, hi2 = (nt & 1) * 2;
                    mma_bf16(acc[mt][nt], aH[mt], bH[ntp][hi2], bH[ntp][hi2 + 1]);
                    mma_bf16(acc[mt][nt], aH[mt], bL[ntp][hi2], bL[ntp][hi2 + 1]);
                    mma_bf16(acc[mt][nt], aL[mt], bH[ntp][hi2], bH[ntp][hi2 + 1]);
                }
        }
        if (k < KK - 1) {
            GATHER(k + 1, buf ^ 1);
            WCOPY(k + 1, buf ^ 1);
        }
        __syncthreads();
    }

    // epilogue: transpose via smem, coalesced NCHW float4 stores
    float* oT = (float*)smem;   // [64][132]
#pragma unroll
    for (int mt = 0; mt < 2; mt++)
#pragma unroll
        for (int nt = 0; nt < 4; nt++) {
            int o = n0 + nt * 8 + (lane & 3) * 2;
            int p = m0 + mt * 16 + (lane >> 2);
            oT[o * 132 + p]           = acc[mt][nt][0];
            oT[(o + 1) * 132 + p]     = acc[mt][nt][1];
            oT[o * 132 + p + 8]       = acc[mt][nt][2];
            oT[(o + 1) * 132 + p + 8] = acc[mt][nt][3];
        }
    __syncthreads();
    {
        size_t obase = (size_t)b * OO * HWIMG + ip0;
        for (int i = tid; i < OO * (MT / 4); i += 256) {
            int o = i >> 5, p4 = i & 31;
            float4 v = *(const float4*)(oT + o * 132 + p4 * 4);
            *(float4*)(out + obase + (size_t)o * HWIMG + p4 * 4) = v;
        }
    }
#undef GATHER
#undef WCOPY
}

// ============== offset conv: coalesced shift-gather + mma.sync (N=32) ==============
#define OFF_SW   65536
#define OFF_SMEM (OFF_SW + 16384)

__global__ void __launch_bounds__(256, 2) k_off_m(const float* __restrict__ b_off) {
    extern __shared__ __align__(1024) char smem[];
    uint32_t sb = smem_u32(smem);

    int tid = threadIdx.x;
    int wid = tid >> 5, lane = tid & 31;
    int m0 = wid * 16;

    int pix0 = blockIdx.x * MT;
    int b = pix0 / HWIMG, ip0 = pix0 % HWIMG;
    const float* xb = g_xn + (size_t)b * HWIMG * CC;
    int lpx = tid >> 4, ck = tid & 15;

    float acc[4][4];
#pragma unroll
    for (int nt = 0; nt < 4; nt++) {
        int o = nt * 8 + (lane & 3) * 2;
        float b0v = (o < TT) ? b_off[o] : 0.f;
        float b1v = (o + 1 < TT) ? b_off[o + 1] : 0.f;
        acc[nt][0] = b0v; acc[nt][1] = b1v;
        acc[nt][2] = b0v; acc[nt][3] = b1v;
    }

#define GATHS(KI, BUF) do {                                                        \
        uint32_t abase_h = sb + ((BUF) * 2 + 0) * 16384;                           \
        uint32_t abase_l = sb + ((BUF) * 2 + 1) * 16384;                           \
        _Pragma("unroll")                                                          \
        for (int ps = 0; ps < 8; ps++) {                                           \
            int px = ps * 16 + lpx;                                                \
            int ip = ip0 + px;                                                     \
            int ph = ip / WW, pw = ip - ph * WW;                                   \
            int y = ph + (KI) / 3 - 1, x = pw + (KI) % 3 - 1;                      \
            float vm = ((unsigned)y < HH && (unsigned)x < WW) ? 1.f : 0.f;         \
            int yc = min(max(y, 0), HH - 1), xc = min(max(x, 0), WW - 1);          \
            float4 v4 = ((const float4*)(xb + (size_t)(yc * WW + xc) * CC))[ck];   \
            float s0 = v4.x * vm, s1 = v4.y * vm, s2 = v4.z * vm, s3 = v4.w * vm;  \
            float h0 = __bfloat162float(__float2bfloat16(s0));                     \
            float h1 = __bfloat162float(__float2bfloat16(s1));                     \
            float h2 = __bfloat162float(__float2bfloat16(s2));                     \
            float h3 = __bfloat162float(__float2bfloat16(s3));                     \
            uint32_t hiA = pack_bf16(s0, s1), hiB = pack_bf16(s2, s3);             \
            uint32_t loA = pack_bf16(s0 - h0, s1 - h1), loB = pack_bf16(s2 - h2, s3 - h3); \
            uint32_t swa = SWZ((uint32_t)(px * 128 + (ck >> 1) * 16)) + (ck & 1) * 8; \
            STS64(abase_h + swa, hiA, hiB);                                        \
            STS64(abase_l + swa, loA, loB);                                        \
        }                                                                          \
    } while (0)

#define WCOPYO(KI, BUF) do {                                                       \
        const uint4* srcw = g_woff4 + (size_t)(KI) * 512;                          \
        uint4* dstw = (uint4*)(smem + OFF_SW + (BUF) * 8192);                      \
        for (int i = tid; i < 512; i += 256) dstw[i] = srcw[i];                    \
    } while (0)

    GATHS(0, 0);
    WCOPYO(0, 0);
    __syncthreads();

#pragma unroll 1
    for (int k = 0; k < KK; k++) {
        int buf = k & 1;
        uint32_t abH = sb + (buf * 2 + 0) * 16384;
        uint32_t abL = sb + (buf * 2 + 1) * 16384;
        uint32_t wbH = sb + OFF_SW + buf * 8192;
        uint32_t wbL = wbH + 4096;
#pragma unroll
        for (int kt = 0; kt < 4; kt++) {
            uint32_t aH[4], aL[4], bH[2][4], bL[2][4];
            ldm4(aH, a_frag_addr(abH, m0, kt, lane));
            ldm4(aL, a_frag_addr(abL, m0, kt, lane));
#pragma unroll
            for (int ntp = 0; ntp < 2; ntp++) {
                ldm4(bH[ntp], b_frag_addr(wbH, ntp * 16, kt, lane));
                ldm4(bL[ntp], b_frag_addr(wbL, ntp * 16, kt, lane));
            }
#pragma unroll
            for (int nt = 0; nt < 4; nt++) {
                int ntp = nt >> 1, hi2 = (nt & 1) * 2;
                mma_bf16(acc[nt], aH, bH[ntp][hi2], bH[ntp][hi2 + 1]);
                mma_bf16(acc[nt], aH, bL[ntp][hi2], bL[ntp][hi2 + 1]);
                mma_bf16(acc[nt], aL, bH[ntp][hi2], bH[ntp][hi2 + 1]);
            }
        }
        if (k < KK - 1) {
            GATHS(k + 1, buf ^ 1);
            WCOPYO(k + 1, buf ^ 1);
        }
        __syncthreads();
    }

    // epilogue: oT[p][o] stride 20, then pack to g_offs[pix][18]
    float* oT = (float*)smem;   // [128][20]
#pragma unroll
    for (int nt = 0; nt < 4; nt++) {
        int o = nt * 8 + (lane & 3) * 2;
        int p = m0 + (lane >> 2);
        if (o < TT) {
            oT[p * 20 + o] = acc[nt][0];
            oT[(p + 8) * 20 + o] = acc[nt][2];
        }
        if (o + 1 < TT) {
            oT[p * 20 + o + 1] = acc[nt][1];
            oT[(p + 8) * 20 + o + 1] = acc[nt][3];
        }
    }
    __syncthreads();
    {
        float* dst = g_offs + (size_t)pix0 * TT;
        for (int i = tid; i < MT * TT; i += 256)
            dst[i] = oT[(i / TT) * 20 + (i % TT)];
    }
#undef GATHS
#undef WCOPYO
}

// ---------------- launch ----------------
extern "C" void kernel_launch(void* const* d_in, const int* in_sizes, int n_in,
                              void* d_out, int out_size) {
    const float* x     = (const float*)d_in[0];
    const float* w_off = (const float*)d_in[1];
    const float* b_off = (const float*)d_in[2];
    const float* w_dc  = (const float*)d_in[3];
    const float* b_dc  = (const float*)d_in[4];
    float* out = (float*)d_out;

    cudaFuncSetAttribute(k_off_m, cudaFuncAttributeMaxDynamicSharedMemorySize, OFF_SMEM);
    cudaFuncSetAttribute(k_main_m, cudaFuncAttributeMaxDynamicSharedMemorySize, MAIN_SMEM);

    k_transpose<<<BB * HH, 256>>>(x);
    k_repack<<<(OO * CC * KK + 255) / 256, 256>>>(w_off, w_dc);
    k_off_m<<<NTIL, 256, OFF_SMEM>>>(b_off);
    k_main_m<<<NTIL, 256, MAIN_SMEM>>>(b_dc, out);
}